// round 13
// baseline (speedup 1.0000x reference)
#include <cuda_runtime.h>
#include <cstdint>
#include <cstddef>

#define SDIM 4096
#define DEPTH 2

// GEMM tiling
#define BM 128
#define BN 128
#define BK 32
#define KITER (SDIM / BK)          // 128
#define ROWSTRIDE 36               // 32 floats + 4 pad: conflict-free STS/LDSM
#define ABUF (BM * ROWSTRIDE)      // 4608 floats per A (or B) buffer
#define BUFPAIR (2 * ABUF)         // A+B per stage
#define NSTAGE 3
#define DSMEM (NSTAGE * BUFPAIR * 4)   // 110592 bytes
#define NTN (SDIM / BN)            // 32 n-tiles

// ---------------- scratch (allocation-free: __device__ globals) ----------------
__device__ __align__(16) float g_A[(size_t)SDIM * SDIM];  // tf32(x + d)
__device__ __align__(16) float g_B[(size_t)SDIM * SDIM];  // tf32(pooler_w)
__device__ float g_part[NTN][SDIM];

__device__ __forceinline__ float gelu_exact(float x) {
    return 0.5f * x * (1.0f + erff(x * 0.70710678118654752440f));
}
__device__ __forceinline__ float tf32r(float v) {
    uint32_t u; asm("cvt.rna.tf32.f32 %0, %1;" : "=r"(u) : "f"(v));
    return __uint_as_float(u);
}
__device__ __forceinline__ uint32_t smem_u32(const void* p) {
    uint32_t a;
    asm("{ .reg .u64 t; cvta.to.shared.u64 t, %1; cvt.u32.u64 %0, t; }" : "=r"(a) : "l"(p));
    return a;
}
__device__ __forceinline__ void mma1688(float& c0, float& c1, float& c2, float& c3,
                                        uint32_t a0, uint32_t a1, uint32_t a2, uint32_t a3,
                                        uint32_t b0, uint32_t b1) {
    asm volatile(
        "mma.sync.aligned.m16n8k8.row.col.f32.tf32.tf32.f32 "
        "{%0,%1,%2,%3}, {%4,%5,%6,%7}, {%8,%9}, {%0,%1,%2,%3};"
        : "+f"(c0), "+f"(c1), "+f"(c2), "+f"(c3)
        : "r"(a0), "r"(a1), "r"(a2), "r"(a3), "r"(b0), "r"(b1));
}
__device__ __forceinline__ void ldsm4(uint32_t& r0, uint32_t& r1, uint32_t& r2,
                                      uint32_t& r3, uint32_t addr) {
    asm volatile("ldmatrix.sync.aligned.m8n8.x4.shared.b16 {%0,%1,%2,%3}, [%4];"
                 : "=r"(r0), "=r"(r1), "=r"(r2), "=r"(r3) : "r"(addr));
}
#define CP_ASYNC16(sa, gp) \
    asm volatile("cp.async.cg.shared.global [%0], [%1], 16;" :: "r"(sa), "l"(gp) : "memory")
#define CP_COMMIT() asm volatile("cp.async.commit_group;" ::: "memory")
#define CP_WAIT1()  asm volatile("cp.async.wait_group 1;" ::: "memory")

// ---------------------------------------------------------------------------
// Kernel 1 (prep): g_A[b][t] = tf32(x[b][t] + d[t]);  g_B[s][t] = tf32(W[s][t])
// d[t] computed inline (collapsed transformer body: size-1 LN == its bias).
// One float4 per thread; first half of grid handles A, second half B.
// ---------------------------------------------------------------------------
#define NV4 (SDIM * SDIM / 4)      // float4 count per matrix: 4194304
__global__ __launch_bounds__(256)
void prep_kernel(const float* __restrict__ x, const float* __restrict__ W,
                 const float* __restrict__ ln1_b, const float* __restrict__ cp1_w,
                 const float* __restrict__ cp1_b, const float* __restrict__ sgu_ln_b,
                 const float* __restrict__ sgu_proj_w, const float* __restrict__ sgu_proj_b,
                 const float* __restrict__ cp2_w, const float* __restrict__ cp2_b) {
    const int gid = blockIdx.x * blockDim.x + threadIdx.x;
    if (gid < NV4) {
        // ---- A: tf32(x + d) ----
        const int t4 = (gid & (SDIM / 4 - 1)) * 4;
        float dv[4] = {0.f, 0.f, 0.f, 0.f};
#pragma unroll
        for (int i = 0; i < DEPTH; i++) {
            const float u = gelu_exact(ln1_b[i] * cp1_w[i * 2] + cp1_b[i * 2]);
            const float coef = u * cp2_w[i];
            const float vc = sgu_ln_b[i];
            const float cb = cp2_b[i];
            float4 pb = *(const float4*)(sgu_proj_b + i * SDIM + t4);
            float v[4] = {pb.x, pb.y, pb.z, pb.w};
            if (vc != 0.0f) {  // generality fallback; never taken with real data
#pragma unroll 1
                for (int e = 0; e < 4; e++) {
                    float rs = 0.0f;
                    const float* row = sgu_proj_w + ((size_t)i * SDIM + (t4 + e)) * SDIM;
                    for (int k = 0; k < SDIM; k++) rs += row[k];
                    v[e] += vc * rs;
                }
            }
#pragma unroll
            for (int e = 0; e < 4; e++) dv[e] += coef * v[e] + cb;
        }
        float4 a = *(const float4*)(x + (size_t)gid * 4);
        float4 o;
        o.x = tf32r(a.x + dv[0]); o.y = tf32r(a.y + dv[1]);
        o.z = tf32r(a.z + dv[2]); o.w = tf32r(a.w + dv[3]);
        *(float4*)(g_A + (size_t)gid * 4) = o;
    } else {
        // ---- B: tf32(W) ----
        const size_t e4 = (size_t)(gid - NV4) * 4;
        float4 b = *(const float4*)(W + e4);
        float4 o;
        o.x = tf32r(b.x); o.y = tf32r(b.y);
        o.z = tf32r(b.z); o.w = tf32r(b.w);
        *(float4*)(g_B + e4) = o;
    }
}

// ---------------------------------------------------------------------------
// cp.async one k-chunk (A+B) into pipeline stage `stage`
// ---------------------------------------------------------------------------
__device__ __forceinline__ void stage_issue(uint32_t sdyn, int stage,
                                            const float* Ab, const float* Bb,
                                            int m0, int col4, int k0) {
#pragma unroll
    for (int i = 0; i < 4; i++) {
        uint32_t off = (uint32_t)((stage * BUFPAIR + (m0 + 32 * i) * ROWSTRIDE + col4 * 4) * 4);
        CP_ASYNC16(sdyn + off, Ab + (size_t)(32 * i) * SDIM + k0);
        CP_ASYNC16(sdyn + off + ABUF * 4, Bb + (size_t)(32 * i) * SDIM + k0);
    }
    CP_COMMIT();
}

// ---------------------------------------------------------------------------
// Kernel 2: tf32 mma.sync GEMM, pure cp.async 3-stage pipeline, ldmatrix frags.
// C[b,s] = sum_t g_A[b,t] * g_B[s,t]; fused gelu(C+pooler_b)*cls_w epilogue.
// 256 threads = 8 warps (2 M x 4 N), warp tile 64x32.
// ---------------------------------------------------------------------------
__global__ __launch_bounds__(256, 2)
void gemm_tc(const float* __restrict__ pooler_b, const float* __restrict__ cls_w) {
    extern __shared__ float smem[];
    const uint32_t sdyn = smem_u32(smem);
    const int tid = threadIdx.x;
    const int lane = tid & 31;
    const int wid = tid >> 5;
    const int warpm = wid >> 2;       // 0..1
    const int warpn = wid & 3;        // 0..3
    const int g = lane >> 2;          // 0..7
    const int cq = lane & 3;          // 0..3

    const int bm = blockIdx.y * BM;
    const int bn = blockIdx.x * BN;

    // producer mapping: col4 = tid%8 (float4 column), rows m0+32i
    const int m0 = tid >> 3;          // 0..31
    const int col4 = tid & 7;         // 0..7
    const float* Ab = g_A + (size_t)(bm + m0) * SDIM + col4 * 4;
    const float* Bb = g_B + (size_t)(bn + m0) * SDIM + col4 * 4;

    // ldmatrix per-lane byte offsets (within a stage buffer)
    const uint32_t a_lane =
        (uint32_t)(((warpm * 64 + (lane & 15)) * ROWSTRIDE + ((lane >> 4) & 1) * 4) * 4);
    const uint32_t b_lane =
        (uint32_t)(((warpn * 32 + ((lane >> 4) & 1) * 8 + (lane & 7)) * ROWSTRIDE
                    + ((lane >> 3) & 1) * 4) * 4 + ABUF * 4);

    float acc[4][4][4];
#pragma unroll
    for (int mt = 0; mt < 4; mt++)
#pragma unroll
        for (int nt = 0; nt < 4; nt++)
#pragma unroll
            for (int e = 0; e < 4; e++) acc[mt][nt][e] = 0.0f;

    // ---- prologue: stages 0 and 1 in flight ----
    stage_issue(sdyn, 0, Ab, Bb, m0, col4, 0);
    stage_issue(sdyn, 1, Ab, Bb, m0, col4, BK);

    int cur = 0;
    for (int kt = 0; kt < KITER; kt++) {
        CP_WAIT1();                   // stage `cur` complete (<=1 group pending)
        __syncthreads();              // visibility + protects buffer being refilled

        if (kt + 2 < KITER) {
            int nst = cur + 2; if (nst >= NSTAGE) nst -= NSTAGE;
            stage_issue(sdyn, nst, Ab, Bb, m0, col4, (kt + 2) * BK);
        }

        const uint32_t base = sdyn + (uint32_t)(cur * BUFPAIR * 4);
#pragma unroll
        for (int ks = 0; ks < 4; ks++) {
            uint32_t af[4][4], bf[4][2];
            const uint32_t ab = base + a_lane + ks * 32;
#pragma unroll
            for (int mt = 0; mt < 4; mt++)
                ldsm4(af[mt][0], af[mt][1], af[mt][2], af[mt][3],
                      ab + mt * (16 * ROWSTRIDE * 4));
            const uint32_t bb = base + b_lane + ks * 32;
            ldsm4(bf[0][0], bf[0][1], bf[1][0], bf[1][1], bb);
            ldsm4(bf[2][0], bf[2][1], bf[3][0], bf[3][1], bb + 16 * ROWSTRIDE * 4);
#pragma unroll
            for (int mt = 0; mt < 4; mt++)
#pragma unroll
                for (int nt = 0; nt < 4; nt++)
                    mma1688(acc[mt][nt][0], acc[mt][nt][1], acc[mt][nt][2], acc[mt][nt][3],
                            af[mt][0], af[mt][1], af[mt][2], af[mt][3],
                            bf[nt][0], bf[nt][1]);
        }
        if (++cur == NSTAGE) cur = 0;
    }

    // ---- fused epilogue: gelu + cls_w dot, deterministic per-n-tile partials ----
    // mma C layout: c0=(g, 2cq), c1=(g, 2cq+1), c2=(g+8, 2cq), c3=(g+8, 2cq+1)
    float rs[8];
#pragma unroll
    for (int i = 0; i < 8; i++) rs[i] = 0.0f;
#pragma unroll
    for (int nt = 0; nt < 4; nt++) {
        const int ncol = bn + warpn * 32 + nt * 8 + 2 * cq;
        const float pb0 = pooler_b[ncol], cw0 = cls_w[ncol];
        const float pb1 = pooler_b[ncol + 1], cw1 = cls_w[ncol + 1];
#pragma unroll
        for (int mt = 0; mt < 4; mt++) {
            rs[2 * mt + 0] += gelu_exact(acc[mt][nt][0] + pb0) * cw0
                            + gelu_exact(acc[mt][nt][1] + pb1) * cw1;
            rs[2 * mt + 1] += gelu_exact(acc[mt][nt][2] + pb0) * cw0
                            + gelu_exact(acc[mt][nt][3] + pb1) * cw1;
        }
    }
#pragma unroll
    for (int off = 1; off <= 2; off <<= 1)
#pragma unroll
        for (int i = 0; i < 8; i++)
            rs[i] += __shfl_xor_sync(0xFFFFFFFF, rs[i], off);

    __syncthreads();                  // staging dead; reuse smem as reduction pad
    float* red = smem;                // [warpn][128 rows]
    if (cq == 0) {
#pragma unroll
        for (int mt = 0; mt < 4; mt++) {
#pragma unroll
            for (int h = 0; h < 2; h++) {
                const int row = warpm * 64 + mt * 16 + h * 8 + g;
                red[warpn * 128 + row] = rs[2 * mt + h];
            }
        }
    }
    __syncthreads();
    if (tid < BM) {
        float s = red[tid] + red[128 + tid] + red[256 + tid] + red[384 + tid];
        g_part[blockIdx.x][bm + tid] = s;
    }
}

// ---------------------------------------------------------------------------
// Kernel 3: logits[b] = cls_b + sum over n-tiles of partials
// ---------------------------------------------------------------------------
__global__ void finalize_kernel(const float* __restrict__ cls_b,
                                float* __restrict__ out) {
    int b = blockIdx.x * blockDim.x + threadIdx.x;
    if (b >= SDIM) return;
    float s = cls_b[0];
#pragma unroll
    for (int t = 0; t < NTN; t++) s += g_part[t][b];
    out[b] = s;
}

// Kernel 4: no-op (launch-count alignment so ncu -s 5 -c 1 captures the GEMM)
__global__ void noop_kernel() {}

// ---------------------------------------------------------------------------
extern "C" void kernel_launch(void* const* d_in, const int* in_sizes, int n_in,
                              void* d_out, int out_size) {
    const float* x          = (const float*)d_in[0];
    const float* ln1_b      = (const float*)d_in[2];
    const float* cp1_w      = (const float*)d_in[3];
    const float* cp1_b      = (const float*)d_in[4];
    const float* sgu_ln_b   = (const float*)d_in[6];
    const float* sgu_proj_w = (const float*)d_in[7];
    const float* sgu_proj_b = (const float*)d_in[8];
    const float* cp2_w      = (const float*)d_in[9];
    const float* cp2_b      = (const float*)d_in[10];
    const float* pooler_w   = (const float*)d_in[11];
    const float* pooler_b   = (const float*)d_in[12];
    const float* cls_w      = (const float*)d_in[13];
    const float* cls_b      = (const float*)d_in[14];
    float* out = (float*)d_out;

    (void)in_sizes; (void)n_in; (void)out_size;

    cudaFuncSetAttribute(gemm_tc, cudaFuncAttributeMaxDynamicSharedMemorySize, DSMEM);

    prep_kernel<<<2 * NV4 / 256, 256>>>(x, pooler_w, ln1_b, cp1_w, cp1_b,
                                        sgu_ln_b, sgu_proj_w, sgu_proj_b,
                                        cp2_w, cp2_b);
    gemm_tc<<<dim3(SDIM / BN, SDIM / BM), 256, DSMEM>>>(pooler_b, cls_w);
    finalize_kernel<<<SDIM / 256, 256>>>(cls_b, out);
    noop_kernel<<<1, 32>>>();
}

// round 14
// speedup vs baseline: 1.6975x; 1.6975x over previous
#include <cuda_runtime.h>
#include <cuda_fp16.h>
#include <cstdint>
#include <cstddef>

#define SDIM 4096
#define DEPTH 2

// GEMM tiling (elements are fp16)
#define BM 128
#define BN 128
#define BK 32                        // halves per k-chunk
#define KITER (SDIM / BK)            // 128
#define ROWH 40                      // row stride in halves (80B): conflict-free
#define ROWB 80
#define ABUF_B (BM * ROWB)           // 10240 bytes per A (or B) stage buffer
#define BUFPAIR_B (2 * ABUF_B)       // 20480
#define NSTAGE 4
#define DSMEM (NSTAGE * BUFPAIR_B)   // 81920 bytes
#define NTN (SDIM / BN)              // 32 n-tiles

// ---------------- scratch (allocation-free: __device__ globals) ----------------
__device__ __align__(16) __half g_A[(size_t)SDIM * SDIM];  // fp16(x + d)
__device__ __align__(16) __half g_B[(size_t)SDIM * SDIM];  // fp16(pooler_w)
__device__ float g_part[NTN][SDIM];

__device__ __forceinline__ float gelu_exact(float x) {
    return 0.5f * x * (1.0f + erff(x * 0.70710678118654752440f));
}
__device__ __forceinline__ uint32_t smem_u32(const void* p) {
    uint32_t a;
    asm("{ .reg .u64 t; cvta.to.shared.u64 t, %1; cvt.u32.u64 %0, t; }" : "=r"(a) : "l"(p));
    return a;
}
__device__ __forceinline__ void mma16816(float& c0, float& c1, float& c2, float& c3,
                                         uint32_t a0, uint32_t a1, uint32_t a2, uint32_t a3,
                                         uint32_t b0, uint32_t b1) {
    asm volatile(
        "mma.sync.aligned.m16n8k16.row.col.f32.f16.f16.f32 "
        "{%0,%1,%2,%3}, {%4,%5,%6,%7}, {%8,%9}, {%0,%1,%2,%3};"
        : "+f"(c0), "+f"(c1), "+f"(c2), "+f"(c3)
        : "r"(a0), "r"(a1), "r"(a2), "r"(a3), "r"(b0), "r"(b1));
}
__device__ __forceinline__ void ldsm4(uint32_t& r0, uint32_t& r1, uint32_t& r2,
                                      uint32_t& r3, uint32_t addr) {
    asm volatile("ldmatrix.sync.aligned.m8n8.x4.shared.b16 {%0,%1,%2,%3}, [%4];"
                 : "=r"(r0), "=r"(r1), "=r"(r2), "=r"(r3) : "r"(addr));
}
#define CP_ASYNC16(sa, gp) \
    asm volatile("cp.async.cg.shared.global [%0], [%1], 16;" :: "r"(sa), "l"(gp) : "memory")
#define CP_COMMIT() asm volatile("cp.async.commit_group;" ::: "memory")
#define CP_WAIT2()  asm volatile("cp.async.wait_group 2;" ::: "memory")

// ---------------------------------------------------------------------------
// Kernel 1 (prep): g_A[b][t] = fp16(x[b][t] + d[t]);  g_B[s][t] = fp16(W[s][t])
// d[t] inline (collapsed transformer body: size-1 layernorm == its bias).
// One 8-element chunk per thread; first half of grid = A, second half = B.
// ---------------------------------------------------------------------------
#define NH8 (SDIM * SDIM / 8)        // 8-half chunks per matrix: 2097152
__global__ __launch_bounds__(256)
void prep_kernel(const float* __restrict__ x, const float* __restrict__ W,
                 const float* __restrict__ ln1_b, const float* __restrict__ cp1_w,
                 const float* __restrict__ cp1_b, const float* __restrict__ sgu_ln_b,
                 const float* __restrict__ sgu_proj_w, const float* __restrict__ sgu_proj_b,
                 const float* __restrict__ cp2_w, const float* __restrict__ cp2_b) {
    const int gid = blockIdx.x * blockDim.x + threadIdx.x;
    __half h[8];
    if (gid < NH8) {
        const size_t e8 = (size_t)gid * 8;
        const int t8 = (int)(e8 & (SDIM - 1));
        float dv[8] = {0.f, 0.f, 0.f, 0.f, 0.f, 0.f, 0.f, 0.f};
#pragma unroll
        for (int i = 0; i < DEPTH; i++) {
            const float u = gelu_exact(ln1_b[i] * cp1_w[i * 2] + cp1_b[i * 2]);
            const float coef = u * cp2_w[i];
            const float vc = sgu_ln_b[i];
            const float cb = cp2_b[i];
            float4 p0 = *(const float4*)(sgu_proj_b + i * SDIM + t8);
            float4 p1 = *(const float4*)(sgu_proj_b + i * SDIM + t8 + 4);
            float v[8] = {p0.x, p0.y, p0.z, p0.w, p1.x, p1.y, p1.z, p1.w};
            if (vc != 0.0f) {  // generality fallback; never taken with real data
#pragma unroll 1
                for (int e = 0; e < 8; e++) {
                    float rs = 0.0f;
                    const float* row = sgu_proj_w + ((size_t)i * SDIM + (t8 + e)) * SDIM;
                    for (int k = 0; k < SDIM; k++) rs += row[k];
                    v[e] += vc * rs;
                }
            }
#pragma unroll
            for (int e = 0; e < 8; e++) dv[e] += coef * v[e] + cb;
        }
        float4 a0 = *(const float4*)(x + e8);
        float4 a1 = *(const float4*)(x + e8 + 4);
        float av[8] = {a0.x, a0.y, a0.z, a0.w, a1.x, a1.y, a1.z, a1.w};
#pragma unroll
        for (int e = 0; e < 8; e++) h[e] = __float2half_rn(av[e] + dv[e]);
        *(uint4*)(g_A + e8) = *(uint4*)h;
    } else {
        const size_t e8 = (size_t)(gid - NH8) * 8;
        float4 b0 = *(const float4*)(W + e8);
        float4 b1 = *(const float4*)(W + e8 + 4);
        float bv[8] = {b0.x, b0.y, b0.z, b0.w, b1.x, b1.y, b1.z, b1.w};
#pragma unroll
        for (int e = 0; e < 8; e++) h[e] = __float2half_rn(bv[e]);
        *(uint4*)(g_B + e8) = *(uint4*)h;
    }
}

// ---------------------------------------------------------------------------
// cp.async one k-chunk (A+B fp16 tiles) into pipeline stage `stage`.
// 256 threads x 4 transfers x 16B = 16KB (A 8KB + B 8KB).
// ---------------------------------------------------------------------------
__device__ __forceinline__ void stage_issue(uint32_t sdyn, int stage,
                                            const __half* Ag, const __half* Bg,
                                            int r0, int col16, int k0) {
    const uint32_t sb = sdyn + (uint32_t)(stage * BUFPAIR_B);
#pragma unroll
    for (int i = 0; i < 2; i++) {
        const int row = r0 + 64 * i;
        const uint32_t off = (uint32_t)(row * ROWB + col16 * 16);
        CP_ASYNC16(sb + off, Ag + (size_t)row * SDIM + k0 + col16 * 8);
        CP_ASYNC16(sb + off + ABUF_B, Bg + (size_t)row * SDIM + k0 + col16 * 8);
    }
    CP_COMMIT();
}

// ---------------------------------------------------------------------------
// Kernel 2: fp16 mma.sync (m16n8k16) GEMM, 4-stage cp.async pipeline.
// C[b,s] = sum_t g_A[b,t]*g_B[s,t]; fused gelu(C+pooler_b)*cls_w epilogue.
// 256 threads = 8 warps (2 M x 4 N), warp tile 64x32.
// ---------------------------------------------------------------------------
__global__ __launch_bounds__(256, 2)
void gemm_tc(const float* __restrict__ pooler_b, const float* __restrict__ cls_w) {
    extern __shared__ float smem[];
    const uint32_t sdyn = smem_u32(smem);
    const int tid = threadIdx.x;
    const int lane = tid & 31;
    const int wid = tid >> 5;
    const int warpm = wid >> 2;       // 0..1
    const int warpn = wid & 3;        // 0..3
    const int g = lane >> 2;          // 0..7
    const int cq = lane & 3;          // 0..3

    const int bm = blockIdx.y * BM;
    const int bn = blockIdx.x * BN;

    // producer mapping: 16B column col16, rows r0 and r0+64
    const int r0 = tid >> 2;          // 0..63
    const int col16 = tid & 3;        // 0..3
    const __half* Ag = g_A + (size_t)bm * SDIM;
    const __half* Bg = g_B + (size_t)bn * SDIM;

    // ldmatrix per-lane byte offsets (within a stage buffer)
    // A: lanes 0-7 rows0-7@k0 -> a0; 8-15 rows8-15@k0 -> a1; 16-23 rows0-7@k8 -> a2; 24-31 -> a3
    const uint32_t a_lane =
        (uint32_t)((warpm * 64 + (lane & 15)) * ROWB + ((lane >> 4) & 1) * 16);
    // B x4 covers 2 n-tiles: lanes0-7 n0-7@k0; 8-15 n0-7@k8; 16-23 n8-15@k0; 24-31 n8-15@k8
    const uint32_t b_lane =
        (uint32_t)((warpn * 32 + (lane & 7) + ((lane >> 4) & 1) * 8) * ROWB
                   + ((lane >> 3) & 1) * 16 + ABUF_B);

    float acc[4][4][4];
#pragma unroll
    for (int mt = 0; mt < 4; mt++)
#pragma unroll
        for (int nt = 0; nt < 4; nt++)
#pragma unroll
            for (int e = 0; e < 4; e++) acc[mt][nt][e] = 0.0f;

    // ---- prologue: 3 stages in flight ----
    stage_issue(sdyn, 0, Ag, Bg, r0, col16, 0);
    stage_issue(sdyn, 1, Ag, Bg, r0, col16, BK);
    stage_issue(sdyn, 2, Ag, Bg, r0, col16, 2 * BK);

    int cur = 0;
    for (int kt = 0; kt < KITER; kt++) {
        CP_WAIT2();                   // stage `cur` complete (<=2 groups pending)
        __syncthreads();

        if (kt + 3 < KITER) {
            int nst = cur + 3; if (nst >= NSTAGE) nst -= NSTAGE;
            stage_issue(sdyn, nst, Ag, Bg, r0, col16, (kt + 3) * BK);
        }

        const uint32_t base = sdyn + (uint32_t)(cur * BUFPAIR_B);
#pragma unroll
        for (int ks = 0; ks < 2; ks++) {          // two k16 steps per 32-chunk
            uint32_t af[4][4], bf[4][2];
            const uint32_t ab = base + a_lane + ks * 32;   // +16 halves
#pragma unroll
            for (int mt = 0; mt < 4; mt++)
                ldsm4(af[mt][0], af[mt][1], af[mt][2], af[mt][3],
                      ab + mt * (16 * ROWB));
            const uint32_t bb = base + b_lane + ks * 32;
            ldsm4(bf[0][0], bf[0][1], bf[1][0], bf[1][1], bb);
            ldsm4(bf[2][0], bf[2][1], bf[3][0], bf[3][1], bb + 16 * ROWB);
#pragma unroll
            for (int mt = 0; mt < 4; mt++)
#pragma unroll
                for (int nt = 0; nt < 4; nt++)
                    mma16816(acc[mt][nt][0], acc[mt][nt][1], acc[mt][nt][2], acc[mt][nt][3],
                             af[mt][0], af[mt][1], af[mt][2], af[mt][3],
                             bf[nt][0], bf[nt][1]);
        }
        if (++cur == NSTAGE) cur = 0;
    }

    // ---- fused epilogue: gelu + cls_w dot, deterministic per-n-tile partials ----
    // mma C layout: c0=(g, 2cq), c1=(g, 2cq+1), c2=(g+8, 2cq), c3=(g+8, 2cq+1)
    float rs[8];
#pragma unroll
    for (int i = 0; i < 8; i++) rs[i] = 0.0f;
#pragma unroll
    for (int nt = 0; nt < 4; nt++) {
        const int ncol = bn + warpn * 32 + nt * 8 + 2 * cq;
        const float pb0 = pooler_b[ncol], cw0 = cls_w[ncol];
        const float pb1 = pooler_b[ncol + 1], cw1 = cls_w[ncol + 1];
#pragma unroll
        for (int mt = 0; mt < 4; mt++) {
            rs[2 * mt + 0] += gelu_exact(acc[mt][nt][0] + pb0) * cw0
                            + gelu_exact(acc[mt][nt][1] + pb1) * cw1;
            rs[2 * mt + 1] += gelu_exact(acc[mt][nt][2] + pb0) * cw0
                            + gelu_exact(acc[mt][nt][3] + pb1) * cw1;
        }
    }
#pragma unroll
    for (int off = 1; off <= 2; off <<= 1)
#pragma unroll
        for (int i = 0; i < 8; i++)
            rs[i] += __shfl_xor_sync(0xFFFFFFFF, rs[i], off);

    __syncthreads();                  // staging dead; reuse smem as reduction pad
    float* red = smem;                // [warpn][128 rows]
    if (cq == 0) {
#pragma unroll
        for (int mt = 0; mt < 4; mt++) {
#pragma unroll
            for (int h = 0; h < 2; h++) {
                const int row = warpm * 64 + mt * 16 + h * 8 + g;
                red[warpn * 128 + row] = rs[2 * mt + h];
            }
        }
    }
    __syncthreads();
    if (tid < BM) {
        float s = red[tid] + red[128 + tid] + red[256 + tid] + red[384 + tid];
        g_part[blockIdx.x][bm + tid] = s;
    }
}

// ---------------------------------------------------------------------------
// Kernel 3: logits[b] = cls_b + sum over n-tiles of partials
// ---------------------------------------------------------------------------
__global__ void finalize_kernel(const float* __restrict__ cls_b,
                                float* __restrict__ out) {
    int b = blockIdx.x * blockDim.x + threadIdx.x;
    if (b >= SDIM) return;
    float s = cls_b[0];
#pragma unroll
    for (int t = 0; t < NTN; t++) s += g_part[t][b];
    out[b] = s;
}

// ---------------------------------------------------------------------------
extern "C" void kernel_launch(void* const* d_in, const int* in_sizes, int n_in,
                              void* d_out, int out_size) {
    const float* x          = (const float*)d_in[0];
    const float* ln1_b      = (const float*)d_in[2];
    const float* cp1_w      = (const float*)d_in[3];
    const float* cp1_b      = (const float*)d_in[4];
    const float* sgu_ln_b   = (const float*)d_in[6];
    const float* sgu_proj_w = (const float*)d_in[7];
    const float* sgu_proj_b = (const float*)d_in[8];
    const float* cp2_w      = (const float*)d_in[9];
    const float* cp2_b      = (const float*)d_in[10];
    const float* pooler_w   = (const float*)d_in[11];
    const float* pooler_b   = (const float*)d_in[12];
    const float* cls_w      = (const float*)d_in[13];
    const float* cls_b      = (const float*)d_in[14];
    float* out = (float*)d_out;

    (void)in_sizes; (void)n_in; (void)out_size;

    cudaFuncSetAttribute(gemm_tc, cudaFuncAttributeMaxDynamicSharedMemorySize, DSMEM);

    prep_kernel<<<2 * NH8 / 256, 256>>>(x, pooler_w, ln1_b, cp1_w, cp1_b,
                                        sgu_ln_b, sgu_proj_w, sgu_proj_b,
                                        cp2_w, cp2_b);
    gemm_tc<<<dim3(SDIM / BN, SDIM / BM), 256, DSMEM>>>(pooler_b, cls_w);
    finalize_kernel<<<SDIM / 256, 256>>>(cls_b, out);
}